// round 15
// baseline (speedup 1.0000x reference)
#include <cuda_runtime.h>
#include <cuda_fp16.h>
#include <math.h>
#include <stdint.h>

// ---------------- problem constants ----------------
#define BATCH 16
#define HH 56
#define WW 56
#define NTOK 3136            // 56*56
#define CDIM 384
#define HEADS 12
#define HD 32
#define WS 7
#define LWIN 49
#define HID 1536
#define MTOT 50176           // BATCH*NTOK = 392*128

// ---------------- scratch (static device memory; no allocations) ----------------
__device__ __align__(256) __half g_xw   [(size_t)MTOT * CDIM];       // LN1 + window partition
__device__ __align__(256) __half g_qkv  [(size_t)MTOT * 3 * CDIM];
__device__ __align__(256) __half g_attn [(size_t)MTOT * CDIM];       // attn out, window order
__device__ __align__(256) float  g_x2   [(size_t)MTOT * CDIM];       // fp32 residual spine
__device__ __align__(256) __half g_xn2  [(size_t)MTOT * CDIM];
__device__ __align__(256) __half g_h1   [(size_t)MTOT * HID];
__device__ __align__(256) __half g_h2   [(size_t)MTOT * HID];
// fp16 transposed weights: Wt[n][k] = W[k][n]
__device__ __align__(256) __half g_wqkv [(size_t)3 * CDIM * CDIM];
__device__ __align__(256) __half g_wproj[(size_t)CDIM * CDIM];
__device__ __align__(256) __half g_wfc1 [(size_t)HID * CDIM];
__device__ __align__(256) __half g_wfc2 [(size_t)CDIM * HID];

// ---------------- helpers ----------------
__device__ __forceinline__ uint32_t smem_u32(const void* p)
{
    uint32_t a;
    asm("{ .reg .u64 t; cvta.to.shared.u64 t, %1; cvt.u32.u64 %0, t; }" : "=r"(a) : "l"(p));
    return a;
}

__device__ __forceinline__ uint32_t f2h2(float a, float b)
{
    __half2 h = __floats2half2_rn(a, b);
    return *(uint32_t*)&h;
}

#define CP_ASYNC16(dst, src) \
    asm volatile("cp.async.cg.shared.global [%0], [%1], 16;" :: "r"(dst), "l"(src))
#define CP_COMMIT() asm volatile("cp.async.commit_group;" ::: "memory")
#define CP_WAIT1()  asm volatile("cp.async.wait_group 1;" ::: "memory")

#define LDSM_X4(r0, r1, r2, r3, addr) \
    asm volatile("ldmatrix.sync.aligned.m8n8.x4.shared.b16 {%0,%1,%2,%3}, [%4];" \
                 : "=r"(r0), "=r"(r1), "=r"(r2), "=r"(r3) : "r"(addr))

#define LDSM_X4_T(r0, r1, r2, r3, addr) \
    asm volatile("ldmatrix.sync.aligned.m8n8.x4.trans.shared.b16 {%0,%1,%2,%3}, [%4];" \
                 : "=r"(r0), "=r"(r1), "=r"(r2), "=r"(r3) : "r"(addr))

#define MMA16816(c, a, b) \
    asm volatile("mma.sync.aligned.m16n8k16.row.col.f32.f16.f16.f32 " \
                 "{%0,%1,%2,%3}, {%4,%5,%6,%7}, {%8,%9}, {%0,%1,%2,%3};" \
                 : "+f"((c)[0]), "+f"((c)[1]), "+f"((c)[2]), "+f"((c)[3]) \
                 : "r"((a)[0]), "r"((a)[1]), "r"((a)[2]), "r"((a)[3]), \
                   "r"((b)[0]), "r"((b)[1]))

// window-order row -> spatial row (window reverse, NO un-shift, per reference)
__device__ __forceinline__ int map_win_to_spatial(int row)
{
    int b  = row / NTOK;
    int t  = row - b * NTOK;
    int wi = t / LWIN;
    int p  = t - wi * LWIN;
    int pr = p / WS;
    int pc = p - pr * WS;
    int h  = (wi >> 3) * WS + pr;
    int w  = (wi & 7)  * WS + pc;
    return b * NTOK + h * WW + w;
}

// ---------------- merged weight prep: all four fp32 [K,N] -> fp16 [N,K] transposes ---------
// segments (32x32 tiles): qkv 36x12=432, proj 12x12=144, fc1 48x12=576, fc2 12x48=576
__global__ __launch_bounds__(256)
void wprep4(const float* __restrict__ Wq, __half* __restrict__ Tq,
            const float* __restrict__ Wp, __half* __restrict__ Tp,
            const float* __restrict__ W1, __half* __restrict__ T1,
            const float* __restrict__ W2, __half* __restrict__ T2)
{
    __shared__ float t[32][33];
    int bidx = blockIdx.x;
    const float* W; __half* Wt; int K, N, nx, r;
    if (bidx < 432)       { W = Wq; Wt = Tq; K = 384;  N = 1152; nx = 36; r = bidx; }
    else if (bidx < 576)  { W = Wp; Wt = Tp; K = 384;  N = 384;  nx = 12; r = bidx - 432; }
    else if (bidx < 1152) { W = W1; Wt = T1; K = 384;  N = 1536; nx = 48; r = bidx - 576; }
    else                  { W = W2; Wt = T2; K = 1536; N = 384;  nx = 12; r = bidx - 1152; }
    int n0 = (r % nx) * 32, k0 = (r / nx) * 32;
    int tx = threadIdx.x, ty = threadIdx.y;   // 32 x 8
#pragma unroll
    for (int i = 0; i < 32; i += 8)
        t[ty + i][tx] = W[(size_t)(k0 + ty + i) * N + n0 + tx];
    __syncthreads();
#pragma unroll
    for (int i = 0; i < 32; i += 8)
        Wt[(size_t)(n0 + ty + i) * K + k0 + tx] = __float2half(t[tx][ty + i]);
}

// ---------------- LayerNorm: warp per row (optionally fused shift + window partition) -------
template <bool SHIFT>
__global__ __launch_bounds__(256)
void ln_kernel(const float* __restrict__ x, const float* __restrict__ g,
               const float* __restrict__ b, __half* __restrict__ out)
{
    const int warp = threadIdx.x >> 5;
    const int lane = threadIdx.x & 31;
    const int row  = blockIdx.x * 8 + warp;
    int srow;
    if (SHIFT) {
        int bb = row / NTOK;
        int t  = row - bb * NTOK;
        int wi = t / LWIN;
        int p  = t - wi * LWIN;
        int pr = p / WS;
        int pc = p - pr * WS;
        int h  = (wi >> 3) * WS + pr + 3; if (h >= HH) h -= HH;
        int w  = (wi & 7)  * WS + pc + 3; if (w >= WW) w -= WW;
        srow = bb * NTOK + h * WW + w;
    } else {
        srow = row;
    }
    const float4* xr = (const float4*)(x + (size_t)srow * CDIM);
    float4 v[3];
    float s = 0.0f, ss = 0.0f;
#pragma unroll
    for (int w = 0; w < 3; w++) {
        v[w] = xr[lane + w * 32];
        s  += v[w].x + v[w].y + v[w].z + v[w].w;
        ss += v[w].x * v[w].x + v[w].y * v[w].y + v[w].z * v[w].z + v[w].w * v[w].w;
    }
#pragma unroll
    for (int off = 16; off; off >>= 1) {
        s  += __shfl_xor_sync(0xffffffffu, s,  off);
        ss += __shfl_xor_sync(0xffffffffu, ss, off);
    }
    const float m   = s * (1.0f / CDIM);
    const float inv = rsqrtf(ss * (1.0f / CDIM) - m * m + 1e-5f);
    uint2* o = (uint2*)(out + (size_t)row * CDIM);
    const float4* gp = (const float4*)g;
    const float4* bp = (const float4*)b;
#pragma unroll
    for (int w = 0; w < 3; w++) {
        float4 gg = gp[lane + w * 32];
        float4 bb = bp[lane + w * 32];
        float o0 = (v[w].x - m) * inv * gg.x + bb.x;
        float o1 = (v[w].y - m) * inv * gg.y + bb.y;
        float o2 = (v[w].z - m) * inv * gg.z + bb.z;
        float o3 = (v[w].w - m) * inv * gg.w + bb.w;
        uint2 u;
        ((__half2*)&u)[0] = __floats2half2_rn(o0, o1);
        ((__half2*)&u)[1] = __floats2half2_rn(o2, o3);
        o[lane + w * 32] = u;
    }
}

// ---------------- fp16 HMMA GEMM: 128x128x64, 3-stage, 2 CTA/SM, smem-staged epilogue ------
// MODE 0: C fp16, no bias    MODE 1: C fp16 + bias
// MODE 2: C fp32 + bias + win->spatial scatter + residual
// MODE 3: C fp32 + bias + residual (same row)
#define BMM 128
#define BNN 128
#define BKK 64
#define STG 3
#define STG_BYTES 16384                   // 128 rows * 128 B
#define GEMM_SMEM (STG * 2 * STG_BYTES)   // 98304 (also >= epilogue stage: 69632)

template <int MODE, int K, int N>
__global__ __launch_bounds__(256, 2)
void hgemm(const __half* __restrict__ A, const __half* __restrict__ Bw,
           void* __restrict__ Cout, const float* __restrict__ bias,
           const float* __restrict__ resid)
{
    extern __shared__ char smem[];
    const uint32_t sA = smem_u32(smem);
    const uint32_t sB = sA + STG * STG_BYTES;

    const int tid  = threadIdx.x;
    const int wid  = tid >> 5;
    const int lane = tid & 31;
    const int bm   = blockIdx.y * BMM;
    const int bn   = blockIdx.x * BNN;
    const int wm0  = (wid & 3) * 32;
    const int wn0  = (wid >> 2) * 64;

    const int lc = tid & 7;
    int   lrow[4];
    uint32_t so[4];
#pragma unroll
    for (int q = 0; q < 4; q++) {
        lrow[q] = (tid + q * 256) >> 3;
        so[q]   = (uint32_t)lrow[q] * 128 + (uint32_t)((lc ^ (lrow[q] & 7)) << 4);
    }

    constexpr int NC = K / BKK;

#pragma unroll
    for (int c = 0; c < 2; c++) {
        const __half* Ag = A  + (size_t)bm * K + c * BKK;
        const __half* Bg = Bw + (size_t)bn * K + c * BKK;
        uint32_t da = sA + c * STG_BYTES;
        uint32_t db = sB + c * STG_BYTES;
#pragma unroll
        for (int q = 0; q < 4; q++) {
            CP_ASYNC16(da + so[q], Ag + (size_t)lrow[q] * K + lc * 8);
            CP_ASYNC16(db + so[q], Bg + (size_t)lrow[q] * K + lc * 8);
        }
        CP_COMMIT();
    }

    float acc[2][8][4];
#pragma unroll
    for (int i = 0; i < 2; i++)
#pragma unroll
        for (int j = 0; j < 8; j++)
#pragma unroll
            for (int r = 0; r < 4; r++) acc[i][j][r] = 0.0f;

    const int a_row_l = (lane & 8) + (lane & 7);
    const int a_chk_l = (lane >> 4) & 1;
    const int b_row_l = (((lane >> 4) & 1) << 3) + (lane & 7);
    const int b_chk_l = (lane >> 3) & 1;

    for (int c = 0; c < NC; c++) {
        const int st = c % STG;
        CP_WAIT1();
        __syncthreads();

        if (c + 2 < NC) {
            const int cc = c + 2, s2 = cc % STG;
            const __half* Ag = A  + (size_t)bm * K + cc * BKK;
            const __half* Bg = Bw + (size_t)bn * K + cc * BKK;
            uint32_t da = sA + s2 * STG_BYTES;
            uint32_t db = sB + s2 * STG_BYTES;
#pragma unroll
            for (int q = 0; q < 4; q++) {
                CP_ASYNC16(da + so[q], Ag + (size_t)lrow[q] * K + lc * 8);
                CP_ASYNC16(db + so[q], Bg + (size_t)lrow[q] * K + lc * 8);
            }
        }
        CP_COMMIT();

        const uint32_t ab = sA + st * STG_BYTES;
        const uint32_t bb = sB + st * STG_BYTES;
#pragma unroll
        for (int ks = 0; ks < 4; ks++) {
            uint32_t a[2][4], b[8][2];
#pragma unroll
            for (int fi = 0; fi < 2; fi++) {
                int row = wm0 + fi * 16 + a_row_l;
                int chk = 2 * ks + a_chk_l;
                uint32_t ad = ab + (uint32_t)row * 128 + (uint32_t)((chk ^ (row & 7)) << 4);
                LDSM_X4(a[fi][0], a[fi][1], a[fi][2], a[fi][3], ad);
            }
#pragma unroll
            for (int nj = 0; nj < 4; nj++) {
                int row = wn0 + nj * 16 + b_row_l;
                int chk = 2 * ks + b_chk_l;
                uint32_t bd = bb + (uint32_t)row * 128 + (uint32_t)((chk ^ (row & 7)) << 4);
                LDSM_X4(b[nj * 2][0], b[nj * 2][1], b[nj * 2 + 1][0], b[nj * 2 + 1][1], bd);
            }
#pragma unroll
            for (int fi = 0; fi < 2; fi++)
#pragma unroll
                for (int j = 0; j < 8; j++)
                    MMA16816(acc[fi][j], a[fi], b[j]);
        }
    }

    // ---------------- epilogue: stage through smem for coalesced global I/O ----------------
    __syncthreads();    // mainloop smem reads complete; safe to reuse buffers
    if (MODE <= 1) {
        // fp16 out: stage at 272 B/row (17x16B; STS banks 4*(lane>>2)+(lane&3) -> conflict-free)
#pragma unroll
        for (int fi = 0; fi < 2; fi++)
#pragma unroll
            for (int h = 0; h < 2; h++) {
                int row = wm0 + fi * 16 + (lane >> 2) + h * 8;
#pragma unroll
                for (int j = 0; j < 8; j++) {
                    int col = wn0 + j * 8 + (lane & 3) * 2;
                    float v0 = acc[fi][j][h * 2];
                    float v1 = acc[fi][j][h * 2 + 1];
                    if (MODE == 1) { v0 += bias[bn + col]; v1 += bias[bn + col + 1]; }
                    *(__half2*)(smem + row * 272 + col * 2) = __floats2half2_rn(v0, v1);
                }
            }
        __syncthreads();
        __half* Ch = (__half*)Cout;
#pragma unroll
        for (int k = 0; k < 8; k++) {
            int idx = tid + k * 256;
            int row = idx >> 4, seg = idx & 15;
            *(uint4*)(Ch + (size_t)(bm + row) * N + bn + seg * 8) =
                *(uint4*)(smem + row * 272 + seg * 16);
        }
    } else {
        // fp32 out + bias + residual (+ scatter): stage at 544 B/row (34x16B)
#pragma unroll
        for (int fi = 0; fi < 2; fi++)
#pragma unroll
            for (int h = 0; h < 2; h++) {
                int row = wm0 + fi * 16 + (lane >> 2) + h * 8;
#pragma unroll
                for (int j = 0; j < 8; j++) {
                    int col = wn0 + j * 8 + (lane & 3) * 2;
                    float2 v;
                    v.x = acc[fi][j][h * 2];
                    v.y = acc[fi][j][h * 2 + 1];
                    *(float2*)(smem + row * 544 + col * 4) = v;
                }
            }
        __syncthreads();
        float* Cf = (float*)Cout;
        const float4 bb4 = *(const float4*)(bias + bn + lane * 4);
        for (int row = wid; row < 128; row += 8) {
            int orow = (MODE == 2) ? map_win_to_spatial(bm + row) : (bm + row);
            float4 v  = *(float4*)(smem + row * 544 + lane * 16);
            float4 rr = *(const float4*)(resid + (size_t)orow * N + bn + lane * 4);
            v.x += bb4.x + rr.x; v.y += bb4.y + rr.y;
            v.z += bb4.z + rr.z; v.w += bb4.w + rr.w;
            *(float4*)(Cf + (size_t)orow * N + bn + lane * 4) = v;
        }
    }
}

// ---------------- windowed attention on tensor cores (Round-12 proven) ----------------
#define ATT_HB 15360                      // per-head smem: 3 tensors * 64 rows * 80 B
#define ATT_SMEM (4 * ATT_HB)             // 61440

__global__ __launch_bounds__(128)
void attn_kernel(const __half* __restrict__ qkv, __half* __restrict__ out)
{
    extern __shared__ char sm[];
    __shared__ int rg[LWIN];
    const int win  = blockIdx.x;
    const int tid  = threadIdx.x;
    const int wid  = tid >> 5;
    const int lane = tid & 31;
    const int head = blockIdx.y * 4 + wid;

    for (int i = tid; i < ATT_SMEM / 16; i += 128)
        *(uint4*)(sm + i * 16) = make_uint4(0u, 0u, 0u, 0u);
    if (tid < LWIN) {
        int wi = win & 63;
        int h = (wi >> 3) * WS + tid / WS;
        int w = (wi & 7)  * WS + tid % WS;
        int sh = (h < HH - WS) ? 0 : ((h < HH - 3) ? 1 : 2);
        int sw = (w < WW - WS) ? 0 : ((w < WW - 3) ? 1 : 2);
        rg[tid] = sh * 3 + sw;
    }
    __syncthreads();

    char* Qs = sm + wid * ATT_HB;
    char* Ks = Qs + 5120;
    char* Vs = Qs + 10240;
    const __half* src = qkv + (size_t)win * LWIN * (3 * CDIM) + head * HD;
    for (int c = lane; c < 196; c += 32) {
        int row = c >> 2, part = c & 3;
        const __half* s = src + (size_t)row * (3 * CDIM) + part * 8;
        *(uint4*)(Qs + row * 80 + part * 16) = *(const uint4*)(s);
        *(uint4*)(Ks + row * 80 + part * 16) = *(const uint4*)(s + CDIM);
        *(uint4*)(Vs + row * 80 + part * 16) = *(const uint4*)(s + 2 * CDIM);
    }
    __syncwarp();

    const uint32_t q32 = smem_u32(Qs), k32 = smem_u32(Ks), v32 = smem_u32(Vs);
    const int a_row = (lane & 8) + (lane & 7);
    const int a_chk = (lane >> 4) & 1;
    const int b_row = (((lane >> 4) & 1) << 3) + (lane & 7);
    const int b_chk = (lane >> 3) & 1;

    float c[4][7][4];
#pragma unroll
    for (int mt = 0; mt < 4; mt++)
#pragma unroll
        for (int nt = 0; nt < 7; nt++)
#pragma unroll
            for (int e = 0; e < 4; e++) c[mt][nt][e] = 0.0f;

#pragma unroll
    for (int kt = 0; kt < 2; kt++) {
        uint32_t qa[4][4], kb[8][2];
#pragma unroll
        for (int mt = 0; mt < 4; mt++)
            LDSM_X4(qa[mt][0], qa[mt][1], qa[mt][2], qa[mt][3],
                    q32 + (uint32_t)(mt * 16 + a_row) * 80 + (uint32_t)(2 * kt + a_chk) * 16);
#pragma unroll
        for (int p = 0; p < 4; p++)
            LDSM_X4(kb[2 * p][0], kb[2 * p][1], kb[2 * p + 1][0], kb[2 * p + 1][1],
                    k32 + (uint32_t)(p * 16 + b_row) * 80 + (uint32_t)(2 * kt + b_chk) * 16);
#pragma unroll
        for (int mt = 0; mt < 4; mt++)
#pragma unroll
            for (int nt = 0; nt < 7; nt++)
                MMA16816(c[mt][nt], qa[mt], kb[nt]);
    }

    const int r_lo = lane >> 2;
    const int c_lo = (lane & 3) << 1;
    const float scale = 0.17677669529663687f;
    int rgr[8];
#pragma unroll
    for (int mt = 0; mt < 4; mt++) {
        int r0 = mt * 16 + r_lo, r1 = r0 + 8;
        rgr[mt * 2]     = rg[r0 < LWIN ? r0 : 48];
        rgr[mt * 2 + 1] = rg[r1 < LWIN ? r1 : 48];
    }
    int  rgc[7][2];
    bool jv[7][2];
#pragma unroll
    for (int nt = 0; nt < 7; nt++)
#pragma unroll
        for (int e = 0; e < 2; e++) {
            int j = nt * 8 + c_lo + e;
            jv[nt][e]  = (j < LWIN);
            rgc[nt][e] = rg[j < LWIN ? j : 48];
        }

    float sum[4][2];
#pragma unroll
    for (int mt = 0; mt < 4; mt++) {
#pragma unroll
        for (int h = 0; h < 2; h++) {
            float m = -1e30f;
#pragma unroll
            for (int nt = 0; nt < 7; nt++)
#pragma unroll
                for (int e = 0; e < 2; e++) {
                    float v = c[mt][nt][h * 2 + e] * scale;
                    if (!jv[nt][e]) v = -1e30f;
                    else if (rgr[mt * 2 + h] != rgc[nt][e]) v -= 100.0f;
                    c[mt][nt][h * 2 + e] = v;
                    m = fmaxf(m, v);
                }
            m = fmaxf(m, __shfl_xor_sync(0xffffffffu, m, 1));
            m = fmaxf(m, __shfl_xor_sync(0xffffffffu, m, 2));
            float s = 0.0f;
#pragma unroll
            for (int nt = 0; nt < 7; nt++)
#pragma unroll
                for (int e = 0; e < 2; e++) {
                    float p = __expf(c[mt][nt][h * 2 + e] - m);
                    c[mt][nt][h * 2 + e] = p;
                    s += p;
                }
            s += __shfl_xor_sync(0xffffffffu, s, 1);
            s += __shfl_xor_sync(0xffffffffu, s, 2);
            sum[mt][h] = s;
        }
    }

    uint32_t ph[4][4][4];
#pragma unroll
    for (int mt = 0; mt < 4; mt++)
#pragma unroll
        for (int k2 = 0; k2 < 4; k2++) {
            int nt0 = 2 * k2, nt1 = nt0 + 1;
            ph[mt][k2][0] = f2h2(c[mt][nt0][0], c[mt][nt0][1]);
            ph[mt][k2][1] = f2h2(c[mt][nt0][2], c[mt][nt0][3]);
            ph[mt][k2][2] = (nt1 < 7) ? f2h2(c[mt][nt1][0], c[mt][nt1][1]) : 0u;
            ph[mt][k2][3] = (nt1 < 7) ? f2h2(c[mt][nt1][2], c[mt][nt1][3]) : 0u;
        }

    float o[4][4][4];
#pragma unroll
    for (int mt = 0; mt < 4; mt++)
#pragma unroll
        for (int nt = 0; nt < 4; nt++)
#pragma unroll
            for (int e = 0; e < 4; e++) o[mt][nt][e] = 0.0f;

    const int vj  = lane & 15;
    const int vdh = ((lane >> 4) & 1) << 4;
#pragma unroll
    for (int kt = 0; kt < 4; kt++) {
        uint32_t vb[4][2];
#pragma unroll
        for (int p = 0; p < 2; p++)
            LDSM_X4_T(vb[2 * p][0], vb[2 * p][1], vb[2 * p + 1][0], vb[2 * p + 1][1],
                      v32 + (uint32_t)(kt * 16 + vj) * 80 + (uint32_t)(p * 32 + vdh));
#pragma unroll
        for (int mt = 0; mt < 4; mt++)
#pragma unroll
            for (int nt = 0; nt < 4; nt++)
                MMA16816(o[mt][nt], ph[mt][kt], vb[nt]);
    }

#pragma unroll
    for (int mt = 0; mt < 4; mt++) {
        float i0 = 1.0f / sum[mt][0];
        float i1 = 1.0f / sum[mt][1];
        int r0 = mt * 16 + r_lo, r1 = r0 + 8;
#pragma unroll
        for (int nt = 0; nt < 4; nt++) {
            int col = head * HD + nt * 8 + c_lo;
            if (r0 < LWIN)
                *(__half2*)(out + (size_t)(win * LWIN + r0) * CDIM + col) =
                    __floats2half2_rn(o[mt][nt][0] * i0, o[mt][nt][1] * i0);
            if (r1 < LWIN)
                *(__half2*)(out + (size_t)(win * LWIN + r1) * CDIM + col) =
                    __floats2half2_rn(o[mt][nt][2] * i1, o[mt][nt][3] * i1);
        }
    }
}

// ---------------- depthwise 3x3 conv: smem-tiled 8x8 pixels x 128 channels + GELU ----------
__global__ __launch_bounds__(256)
void dwconv_gelu(const __half* __restrict__ x, const float* __restrict__ kern,
                 const float* __restrict__ bias, __half* __restrict__ out)
{
    __shared__ __half2 s[64][101];
    const int cb   = blockIdx.x;
    const int tile = blockIdx.y;
    const int b    = blockIdx.z;
    const int th0  = (tile / 7) * 8;
    const int tw0  = (tile % 7) * 8;
    const int ch0  = cb * 128;
    const int tid  = threadIdx.x;

    for (int idx = tid; idx < 100 * 64; idx += 256) {
        int loc = idx >> 6;
        int pr  = idx & 63;
        int ly = loc / 10 - 1, lx = loc - (loc / 10) * 10 - 1;
        int ih = th0 + ly, iw = tw0 + lx;
        __half2 v = __float2half2_rn(0.0f);
        if ((unsigned)ih < HH && (unsigned)iw < WW)
            v = *(const __half2*)(x + ((size_t)b * NTOK + ih * WW + iw) * HID + ch0 + pr * 2);
        s[pr][loc] = v;
    }
    __syncthreads();

    const int pr = tid & 63;
    const int g  = tid >> 6;
    const int ch = ch0 + pr * 2;
    float k0[9], k1[9];
#pragma unroll
    for (int i = 0; i < 9; i++) { k0[i] = kern[ch * 9 + i]; k1[i] = kern[ch * 9 + 9 + i]; }
    float2 bb = *(const float2*)(bias + ch);

#pragma unroll
    for (int pp = 0; pp < 16; pp++) {
        int pix = g * 16 + pp;
        int py = pix >> 3, px = pix & 7;
        float a0 = bb.x, a1 = bb.y;
#pragma unroll
        for (int dh = 0; dh < 3; dh++)
#pragma unroll
            for (int dw = 0; dw < 3; dw++) {
                float2 v = __half22float2(s[pr][(py + dh) * 10 + px + dw]);
                a0 = fmaf(v.x, k0[dh * 3 + dw], a0);
                a1 = fmaf(v.y, k1[dh * 3 + dw], a1);
            }
        float g0 = 0.5f * a0 * (1.0f + erff(a0 * 0.70710678118654752f));
        float g1 = 0.5f * a1 * (1.0f + erff(a1 * 0.70710678118654752f));
        *(__half2*)(out + ((size_t)b * NTOK + (th0 + py) * WW + tw0 + px) * HID + ch) =
            __floats2half2_rn(g0, g1);
    }
}

// ---------------- launcher ----------------
extern "C" void kernel_launch(void* const* d_in, const int* in_sizes, int n_in,
                              void* d_out, int out_size)
{
    const float* x     = (const float*)d_in[0];
    const float* ln1g  = (const float*)d_in[1];
    const float* ln1b  = (const float*)d_in[2];
    const float* qkvw  = (const float*)d_in[3];
    const float* projw = (const float*)d_in[4];
    const float* projb = (const float*)d_in[5];
    const float* ln2g  = (const float*)d_in[6];
    const float* ln2b  = (const float*)d_in[7];
    const float* fc1w  = (const float*)d_in[8];
    const float* fc1b  = (const float*)d_in[9];
    const float* dwk   = (const float*)d_in[10];
    const float* dwb   = (const float*)d_in[11];
    const float* fc2w  = (const float*)d_in[12];
    const float* fc2b  = (const float*)d_in[13];
    float* out = (float*)d_out;

    __half *xw, *qkv, *attn, *xn2, *h1, *h2, *wqkv, *wproj, *wfc1, *wfc2;
    float  *x2;
    cudaGetSymbolAddress((void**)&xw,    g_xw);
    cudaGetSymbolAddress((void**)&qkv,   g_qkv);
    cudaGetSymbolAddress((void**)&attn,  g_attn);
    cudaGetSymbolAddress((void**)&x2,    g_x2);
    cudaGetSymbolAddress((void**)&xn2,   g_xn2);
    cudaGetSymbolAddress((void**)&h1,    g_h1);
    cudaGetSymbolAddress((void**)&h2,    g_h2);
    cudaGetSymbolAddress((void**)&wqkv,  g_wqkv);
    cudaGetSymbolAddress((void**)&wproj, g_wproj);
    cudaGetSymbolAddress((void**)&wfc1,  g_wfc1);
    cudaGetSymbolAddress((void**)&wfc2,  g_wfc2);

    cudaFuncSetAttribute(hgemm<0, CDIM, 3 * CDIM>, cudaFuncAttributeMaxDynamicSharedMemorySize, GEMM_SMEM);
    cudaFuncSetAttribute(hgemm<2, CDIM, CDIM>,     cudaFuncAttributeMaxDynamicSharedMemorySize, GEMM_SMEM);
    cudaFuncSetAttribute(hgemm<1, CDIM, HID>,      cudaFuncAttributeMaxDynamicSharedMemorySize, GEMM_SMEM);
    cudaFuncSetAttribute(hgemm<3, HID, CDIM>,      cudaFuncAttributeMaxDynamicSharedMemorySize, GEMM_SMEM);
    cudaFuncSetAttribute(attn_kernel,              cudaFuncAttributeMaxDynamicSharedMemorySize, ATT_SMEM);

    // 0: all weight preps (merged)
    wprep4<<<1728, dim3(32, 8)>>>(qkvw, wqkv, projw, wproj, fc1w, wfc1, fc2w, wfc2);
    // 1: LN1 + roll(-3,-3) + window partition (fp16 out)
    ln_kernel<true><<<MTOT / 8, 256>>>(x, ln1g, ln1b, xw);
    // 2: QKV GEMM
    hgemm<0, CDIM, 3 * CDIM><<<dim3(9, MTOT / 128), 256, GEMM_SMEM>>>(xw, wqkv, qkv, (const float*)0, (const float*)0);
    // 3: windowed attention (tensor cores, analytic shift mask)
    attn_kernel<<<dim3(1024, 3), 128, ATT_SMEM>>>(qkv, attn);
    // 4: proj GEMM + bias + window-reverse scatter + residual(x) -> x2 (fp32)
    hgemm<2, CDIM, CDIM><<<dim3(3, MTOT / 128), 256, GEMM_SMEM>>>(attn, wproj, x2, projb, x);
    // 5: LN2 (fp16 out)
    ln_kernel<false><<<MTOT / 8, 256>>>(x2, ln2g, ln2b, xn2);
    // 6: fc1 GEMM + bias
    hgemm<1, CDIM, HID><<<dim3(12, MTOT / 128), 256, GEMM_SMEM>>>(xn2, wfc1, h1, fc1b, (const float*)0);
    // 7: depthwise conv + bias + exact GELU (smem-tiled)
    dwconv_gelu<<<dim3(12, 49, BATCH), 256>>>(h1, dwk, dwb, h2);
    // 8: fc2 GEMM + bias + residual(x2) -> out (fp32)
    hgemm<3, HID, CDIM><<<dim3(3, MTOT / 128), 256, GEMM_SMEM>>>(h2, wfc2, out, fc2b, x2);
}

// round 16
// speedup vs baseline: 1.0244x; 1.0244x over previous
#include <cuda_runtime.h>
#include <cuda_fp16.h>
#include <math.h>
#include <stdint.h>

// ---------------- problem constants ----------------
#define BATCH 16
#define HH 56
#define WW 56
#define NTOK 3136            // 56*56
#define CDIM 384
#define HEADS 12
#define HD 32
#define WS 7
#define LWIN 49
#define HID 1536
#define MTOT 50176           // BATCH*NTOK = 392*128

// ---------------- scratch (static device memory; no allocations) ----------------
__device__ __align__(256) __half g_xw   [(size_t)MTOT * CDIM];       // LN1 + window partition
__device__ __align__(256) __half g_qkv  [(size_t)MTOT * 3 * CDIM];
__device__ __align__(256) __half g_attn [(size_t)MTOT * CDIM];       // attn out, window order
__device__ __align__(256) float  g_x2   [(size_t)MTOT * CDIM];       // fp32 residual spine
__device__ __align__(256) __half g_xn2  [(size_t)MTOT * CDIM];
__device__ __align__(256) __half g_h1   [(size_t)MTOT * HID];
__device__ __align__(256) __half g_h2   [(size_t)MTOT * HID];
// fp16 transposed weights: Wt[n][k] = W[k][n]
__device__ __align__(256) __half g_wqkv [(size_t)3 * CDIM * CDIM];
__device__ __align__(256) __half g_wproj[(size_t)CDIM * CDIM];
__device__ __align__(256) __half g_wfc1 [(size_t)HID * CDIM];
__device__ __align__(256) __half g_wfc2 [(size_t)CDIM * HID];

// ---------------- helpers ----------------
__device__ __forceinline__ uint32_t smem_u32(const void* p)
{
    uint32_t a;
    asm("{ .reg .u64 t; cvta.to.shared.u64 t, %1; cvt.u32.u64 %0, t; }" : "=r"(a) : "l"(p));
    return a;
}

__device__ __forceinline__ uint32_t f2h2(float a, float b)
{
    __half2 h = __floats2half2_rn(a, b);
    return *(uint32_t*)&h;
}

#define CP_ASYNC16(dst, src) \
    asm volatile("cp.async.cg.shared.global [%0], [%1], 16;" :: "r"(dst), "l"(src))
#define CP_COMMIT() asm volatile("cp.async.commit_group;" ::: "memory")
#define CP_WAIT1()  asm volatile("cp.async.wait_group 1;" ::: "memory")

#define LDSM_X4(r0, r1, r2, r3, addr) \
    asm volatile("ldmatrix.sync.aligned.m8n8.x4.shared.b16 {%0,%1,%2,%3}, [%4];" \
                 : "=r"(r0), "=r"(r1), "=r"(r2), "=r"(r3) : "r"(addr))

#define LDSM_X4_T(r0, r1, r2, r3, addr) \
    asm volatile("ldmatrix.sync.aligned.m8n8.x4.trans.shared.b16 {%0,%1,%2,%3}, [%4];" \
                 : "=r"(r0), "=r"(r1), "=r"(r2), "=r"(r3) : "r"(addr))

#define MMA16816(c, a, b) \
    asm volatile("mma.sync.aligned.m16n8k16.row.col.f32.f16.f16.f32 " \
                 "{%0,%1,%2,%3}, {%4,%5,%6,%7}, {%8,%9}, {%0,%1,%2,%3};" \
                 : "+f"((c)[0]), "+f"((c)[1]), "+f"((c)[2]), "+f"((c)[3]) \
                 : "r"((a)[0]), "r"((a)[1]), "r"((a)[2]), "r"((a)[3]), \
                   "r"((b)[0]), "r"((b)[1]))

// window-order row -> spatial row (window reverse, NO un-shift, per reference)
__device__ __forceinline__ int map_win_to_spatial(int row)
{
    int b  = row / NTOK;
    int t  = row - b * NTOK;
    int wi = t / LWIN;
    int p  = t - wi * LWIN;
    int pr = p / WS;
    int pc = p - pr * WS;
    int h  = (wi >> 3) * WS + pr;
    int w  = (wi & 7)  * WS + pc;
    return b * NTOK + h * WW + w;
}

// ---------------- merged weight prep: all four fp32 [K,N] -> fp16 [N,K] transposes ---------
__global__ __launch_bounds__(256)
void wprep4(const float* __restrict__ Wq, __half* __restrict__ Tq,
            const float* __restrict__ Wp, __half* __restrict__ Tp,
            const float* __restrict__ W1, __half* __restrict__ T1,
            const float* __restrict__ W2, __half* __restrict__ T2)
{
    __shared__ float t[32][33];
    int bidx = blockIdx.x;
    const float* W; __half* Wt; int K, N, nx, r;
    if (bidx < 432)       { W = Wq; Wt = Tq; K = 384;  N = 1152; nx = 36; r = bidx; }
    else if (bidx < 576)  { W = Wp; Wt = Tp; K = 384;  N = 384;  nx = 12; r = bidx - 432; }
    else if (bidx < 1152) { W = W1; Wt = T1; K = 384;  N = 1536; nx = 48; r = bidx - 576; }
    else                  { W = W2; Wt = T2; K = 1536; N = 384;  nx = 12; r = bidx - 1152; }
    int n0 = (r % nx) * 32, k0 = (r / nx) * 32;
    int tx = threadIdx.x, ty = threadIdx.y;   // 32 x 8
#pragma unroll
    for (int i = 0; i < 32; i += 8)
        t[ty + i][tx] = W[(size_t)(k0 + ty + i) * N + n0 + tx];
    __syncthreads();
#pragma unroll
    for (int i = 0; i < 32; i += 8)
        Wt[(size_t)(n0 + ty + i) * K + k0 + tx] = __float2half(t[tx][ty + i]);
}

// ---------------- LayerNorm: warp per row (optionally fused shift + window partition) -------
template <bool SHIFT>
__global__ __launch_bounds__(256)
void ln_kernel(const float* __restrict__ x, const float* __restrict__ g,
               const float* __restrict__ b, __half* __restrict__ out)
{
    const int warp = threadIdx.x >> 5;
    const int lane = threadIdx.x & 31;
    const int row  = blockIdx.x * 8 + warp;
    int srow;
    if (SHIFT) {
        int bb = row / NTOK;
        int t  = row - bb * NTOK;
        int wi = t / LWIN;
        int p  = t - wi * LWIN;
        int pr = p / WS;
        int pc = p - pr * WS;
        int h  = (wi >> 3) * WS + pr + 3; if (h >= HH) h -= HH;
        int w  = (wi & 7)  * WS + pc + 3; if (w >= WW) w -= WW;
        srow = bb * NTOK + h * WW + w;
    } else {
        srow = row;
    }
    const float4* xr = (const float4*)(x + (size_t)srow * CDIM);
    float4 v[3];
    float s = 0.0f, ss = 0.0f;
#pragma unroll
    for (int w = 0; w < 3; w++) {
        v[w] = xr[lane + w * 32];
        s  += v[w].x + v[w].y + v[w].z + v[w].w;
        ss += v[w].x * v[w].x + v[w].y * v[w].y + v[w].z * v[w].z + v[w].w * v[w].w;
    }
#pragma unroll
    for (int off = 16; off; off >>= 1) {
        s  += __shfl_xor_sync(0xffffffffu, s,  off);
        ss += __shfl_xor_sync(0xffffffffu, ss, off);
    }
    const float m   = s * (1.0f / CDIM);
    const float inv = rsqrtf(ss * (1.0f / CDIM) - m * m + 1e-5f);
    uint2* o = (uint2*)(out + (size_t)row * CDIM);
    const float4* gp = (const float4*)g;
    const float4* bp = (const float4*)b;
#pragma unroll
    for (int w = 0; w < 3; w++) {
        float4 gg = gp[lane + w * 32];
        float4 bb = bp[lane + w * 32];
        float o0 = (v[w].x - m) * inv * gg.x + bb.x;
        float o1 = (v[w].y - m) * inv * gg.y + bb.y;
        float o2 = (v[w].z - m) * inv * gg.z + bb.z;
        float o3 = (v[w].w - m) * inv * gg.w + bb.w;
        uint2 u;
        ((__half2*)&u)[0] = __floats2half2_rn(o0, o1);
        ((__half2*)&u)[1] = __floats2half2_rn(o2, o3);
        o[lane + w * 32] = u;
    }
}

// ---------------- fp16 HMMA GEMM: 128x128x64, 3-stage, 2 CTA/SM, smem-staged epilogue ------
#define BMM 128
#define BNN 128
#define BKK 64
#define STG 3
#define STG_BYTES 16384                   // 128 rows * 128 B
#define GEMM_SMEM (STG * 2 * STG_BYTES)   // 98304

template <int MODE, int K, int N>
__global__ __launch_bounds__(256, 2)
void hgemm(const __half* __restrict__ A, const __half* __restrict__ Bw,
           void* __restrict__ Cout, const float* __restrict__ bias,
           const float* __restrict__ resid)
{
    extern __shared__ char smem[];
    const uint32_t sA = smem_u32(smem);
    const uint32_t sB = sA + STG * STG_BYTES;

    const int tid  = threadIdx.x;
    const int wid  = tid >> 5;
    const int lane = tid & 31;
    const int bm   = blockIdx.y * BMM;
    const int bn   = blockIdx.x * BNN;
    const int wm0  = (wid & 3) * 32;
    const int wn0  = (wid >> 2) * 64;

    const int lc = tid & 7;
    int   lrow[4];
    uint32_t so[4];
#pragma unroll
    for (int q = 0; q < 4; q++) {
        lrow[q] = (tid + q * 256) >> 3;
        so[q]   = (uint32_t)lrow[q] * 128 + (uint32_t)((lc ^ (lrow[q] & 7)) << 4);
    }

    constexpr int NC = K / BKK;

#pragma unroll
    for (int c = 0; c < 2; c++) {
        const __half* Ag = A  + (size_t)bm * K + c * BKK;
        const __half* Bg = Bw + (size_t)bn * K + c * BKK;
        uint32_t da = sA + c * STG_BYTES;
        uint32_t db = sB + c * STG_BYTES;
#pragma unroll
        for (int q = 0; q < 4; q++) {
            CP_ASYNC16(da + so[q], Ag + (size_t)lrow[q] * K + lc * 8);
            CP_ASYNC16(db + so[q], Bg + (size_t)lrow[q] * K + lc * 8);
        }
        CP_COMMIT();
    }

    float acc[2][8][4];
#pragma unroll
    for (int i = 0; i < 2; i++)
#pragma unroll
        for (int j = 0; j < 8; j++)
#pragma unroll
            for (int r = 0; r < 4; r++) acc[i][j][r] = 0.0f;

    const int a_row_l = (lane & 8) + (lane & 7);
    const int a_chk_l = (lane >> 4) & 1;
    const int b_row_l = (((lane >> 4) & 1) << 3) + (lane & 7);
    const int b_chk_l = (lane >> 3) & 1;

    for (int c = 0; c < NC; c++) {
        const int st = c % STG;
        CP_WAIT1();
        __syncthreads();

        if (c + 2 < NC) {
            const int cc = c + 2, s2 = cc % STG;
            const __half* Ag = A  + (size_t)bm * K + cc * BKK;
            const __half* Bg = Bw + (size_t)bn * K + cc * BKK;
            uint32_t da = sA + s2 * STG_BYTES;
            uint32_t db = sB + s2 * STG_BYTES;
#pragma unroll
            for (int q = 0; q < 4; q++) {
                CP_ASYNC16(da + so[q], Ag + (size_t)lrow[q] * K + lc * 8);
                CP_ASYNC16(db + so[q], Bg + (size_t)lrow[q] * K + lc * 8);
            }
        }
        CP_COMMIT();

        const uint32_t ab = sA + st * STG_BYTES;
        const uint32_t bb = sB + st * STG_BYTES;
#pragma unroll
        for (int ks = 0; ks < 4; ks++) {
            uint32_t a[2][4], b[8][2];
#pragma unroll
            for (int fi = 0; fi < 2; fi++) {
                int row = wm0 + fi * 16 + a_row_l;
                int chk = 2 * ks + a_chk_l;
                uint32_t ad = ab + (uint32_t)row * 128 + (uint32_t)((chk ^ (row & 7)) << 4);
                LDSM_X4(a[fi][0], a[fi][1], a[fi][2], a[fi][3], ad);
            }
#pragma unroll
            for (int nj = 0; nj < 4; nj++) {
                int row = wn0 + nj * 16 + b_row_l;
                int chk = 2 * ks + b_chk_l;
                uint32_t bd = bb + (uint32_t)row * 128 + (uint32_t)((chk ^ (row & 7)) << 4);
                LDSM_X4(b[nj * 2][0], b[nj * 2][1], b[nj * 2 + 1][0], b[nj * 2 + 1][1], bd);
            }
#pragma unroll
            for (int fi = 0; fi < 2; fi++)
#pragma unroll
                for (int j = 0; j < 8; j++)
                    MMA16816(acc[fi][j], a[fi], b[j]);
        }
    }

    // ---------------- epilogue: stage through smem for coalesced global I/O ----------------
    __syncthreads();
    if (MODE <= 1) {
#pragma unroll
        for (int fi = 0; fi < 2; fi++)
#pragma unroll
            for (int h = 0; h < 2; h++) {
                int row = wm0 + fi * 16 + (lane >> 2) + h * 8;
#pragma unroll
                for (int j = 0; j < 8; j++) {
                    int col = wn0 + j * 8 + (lane & 3) * 2;
                    float v0 = acc[fi][j][h * 2];
                    float v1 = acc[fi][j][h * 2 + 1];
                    if (MODE == 1) { v0 += bias[bn + col]; v1 += bias[bn + col + 1]; }
                    *(__half2*)(smem + row * 272 + col * 2) = __floats2half2_rn(v0, v1);
                }
            }
        __syncthreads();
        __half* Ch = (__half*)Cout;
#pragma unroll
        for (int k = 0; k < 8; k++) {
            int idx = tid + k * 256;
            int row = idx >> 4, seg = idx & 15;
            *(uint4*)(Ch + (size_t)(bm + row) * N + bn + seg * 8) =
                *(uint4*)(smem + row * 272 + seg * 16);
        }
    } else {
#pragma unroll
        for (int fi = 0; fi < 2; fi++)
#pragma unroll
            for (int h = 0; h < 2; h++) {
                int row = wm0 + fi * 16 + (lane >> 2) + h * 8;
#pragma unroll
                for (int j = 0; j < 8; j++) {
                    int col = wn0 + j * 8 + (lane & 3) * 2;
                    float2 v;
                    v.x = acc[fi][j][h * 2];
                    v.y = acc[fi][j][h * 2 + 1];
                    *(float2*)(smem + row * 544 + col * 4) = v;
                }
            }
        __syncthreads();
        float* Cf = (float*)Cout;
        const float4 bb4 = *(const float4*)(bias + bn + lane * 4);
        for (int row = wid; row < 128; row += 8) {
            int orow = (MODE == 2) ? map_win_to_spatial(bm + row) : (bm + row);
            float4 v  = *(float4*)(smem + row * 544 + lane * 16);
            float4 rr = *(const float4*)(resid + (size_t)orow * N + bn + lane * 4);
            v.x += bb4.x + rr.x; v.y += bb4.y + rr.y;
            v.z += bb4.z + rr.z; v.w += bb4.w + rr.w;
            *(float4*)(Cf + (size_t)orow * N + bn + lane * 4) = v;
        }
    }
}

// ---------------- windowed attention on tensor cores ----------------
// min-blocks 3 for occupancy; only V pad rows (49..63) are zeroed — Q/K pad garbage
// is provably overwritten by the jv mask / discarded rows before it can matter.
#define ATT_HB 15360                      // per-head smem: 3 tensors * 64 rows * 80 B
#define ATT_SMEM (4 * ATT_HB)             // 61440

__global__ __launch_bounds__(128, 3)
void attn_kernel(const __half* __restrict__ qkv, __half* __restrict__ out)
{
    extern __shared__ char sm[];
    __shared__ int rg[LWIN];
    const int win  = blockIdx.x;
    const int tid  = threadIdx.x;
    const int wid  = tid >> 5;
    const int lane = tid & 31;
    const int head = blockIdx.y * 4 + wid;

    if (tid < LWIN) {
        int wi = win & 63;
        int h = (wi >> 3) * WS + tid / WS;
        int w = (wi & 7)  * WS + tid % WS;
        int sh = (h < HH - WS) ? 0 : ((h < HH - 3) ? 1 : 2);
        int sw = (w < WW - WS) ? 0 : ((w < WW - 3) ? 1 : 2);
        rg[tid] = sh * 3 + sw;
    }

    char* Qs = sm + wid * ATT_HB;
    char* Ks = Qs + 5120;
    char* Vs = Qs + 10240;
    // zero ONLY V pad rows 49..63 (75 x 16B per head)
    for (int i = lane; i < 75; i += 32)
        *(uint4*)(Vs + 49 * 80 + i * 16) = make_uint4(0u, 0u, 0u, 0u);
    const __half* src = qkv + (size_t)win * LWIN * (3 * CDIM) + head * HD;
    for (int c = lane; c < 196; c += 32) {
        int row = c >> 2, part = c & 3;
        const __half* s = src + (size_t)row * (3 * CDIM) + part * 8;
        *(uint4*)(Qs + row * 80 + part * 16) = *(const uint4*)(s);
        *(uint4*)(Ks + row * 80 + part * 16) = *(const uint4*)(s + CDIM);
        *(uint4*)(Vs + row * 80 + part * 16) = *(const uint4*)(s + 2 * CDIM);
    }
    __syncthreads();   // rg is block-shared; smem tiles are warp-local

    const uint32_t q32 = smem_u32(Qs), k32 = smem_u32(Ks), v32 = smem_u32(Vs);
    const int a_row = (lane & 8) + (lane & 7);
    const int a_chk = (lane >> 4) & 1;
    const int b_row = (((lane >> 4) & 1) << 3) + (lane & 7);
    const int b_chk = (lane >> 3) & 1;

    float c[4][7][4];
#pragma unroll
    for (int mt = 0; mt < 4; mt++)
#pragma unroll
        for (int nt = 0; nt < 7; nt++)
#pragma unroll
            for (int e = 0; e < 4; e++) c[mt][nt][e] = 0.0f;

#pragma unroll
    for (int kt = 0; kt < 2; kt++) {
        uint32_t qa[4][4], kb[8][2];
#pragma unroll
        for (int mt = 0; mt < 4; mt++)
            LDSM_X4(qa[mt][0], qa[mt][1], qa[mt][2], qa[mt][3],
                    q32 + (uint32_t)(mt * 16 + a_row) * 80 + (uint32_t)(2 * kt + a_chk) * 16);
#pragma unroll
        for (int p = 0; p < 4; p++)
            LDSM_X4(kb[2 * p][0], kb[2 * p][1], kb[2 * p + 1][0], kb[2 * p + 1][1],
                    k32 + (uint32_t)(p * 16 + b_row) * 80 + (uint32_t)(2 * kt + b_chk) * 16);
#pragma unroll
        for (int mt = 0; mt < 4; mt++)
#pragma unroll
            for (int nt = 0; nt < 7; nt++)
                MMA16816(c[mt][nt], qa[mt], kb[nt]);
    }

    const int r_lo = lane >> 2;
    const int c_lo = (lane & 3) << 1;
    const float scale = 0.17677669529663687f;
    int rgr[8];
#pragma unroll
    for (int mt = 0; mt < 4; mt++) {
        int r0 = mt * 16 + r_lo, r1 = r0 + 8;
        rgr[mt * 2]     = rg[r0 < LWIN ? r0 : 48];
        rgr[mt * 2 + 1] = rg[r1 < LWIN ? r1 : 48];
    }
    int  rgc[7][2];
    bool jv[7][2];
#pragma unroll
    for (int nt = 0; nt < 7; nt++)
#pragma unroll
        for (int e = 0; e < 2; e++) {
            int j = nt * 8 + c_lo + e;
            jv[nt][e]  = (j < LWIN);
            rgc[nt][e] = rg[j < LWIN ? j : 48];
        }

    float sum[4][2];
#pragma unroll
    for (int mt = 0; mt < 4; mt++) {
#pragma unroll
        for (int h = 0; h < 2; h++) {
            float m = -1e30f;
#pragma unroll
            for (int nt = 0; nt < 7; nt++)
#pragma unroll
                for (int e = 0; e < 2; e++) {
                    float v = c[mt][nt][h * 2 + e] * scale;
                    if (!jv[nt][e]) v = -1e30f;
                    else if (rgr[mt * 2 + h] != rgc[nt][e]) v -= 100.0f;
                    c[mt][nt][h * 2 + e] = v;
                    m = fmaxf(m, v);
                }
            m = fmaxf(m, __shfl_xor_sync(0xffffffffu, m, 1));
            m = fmaxf(m, __shfl_xor_sync(0xffffffffu, m, 2));
            float s = 0.0f;
#pragma unroll
            for (int nt = 0; nt < 7; nt++)
#pragma unroll
                for (int e = 0; e < 2; e++) {
                    float p = __expf(c[mt][nt][h * 2 + e] - m);
                    c[mt][nt][h * 2 + e] = p;
                    s += p;
                }
            s += __shfl_xor_sync(0xffffffffu, s, 1);
            s += __shfl_xor_sync(0xffffffffu, s, 2);
            sum[mt][h] = s;
        }
    }

    uint32_t ph[4][4][4];
#pragma unroll
    for (int mt = 0; mt < 4; mt++)
#pragma unroll
        for (int k2 = 0; k2 < 4; k2++) {
            int nt0 = 2 * k2, nt1 = nt0 + 1;
            ph[mt][k2][0] = f2h2(c[mt][nt0][0], c[mt][nt0][1]);
            ph[mt][k2][1] = f2h2(c[mt][nt0][2], c[mt][nt0][3]);
            ph[mt][k2][2] = (nt1 < 7) ? f2h2(c[mt][nt1][0], c[mt][nt1][1]) : 0u;
            ph[mt][k2][3] = (nt1 < 7) ? f2h2(c[mt][nt1][2], c[mt][nt1][3]) : 0u;
        }

    float o[4][4][4];
#pragma unroll
    for (int mt = 0; mt < 4; mt++)
#pragma unroll
        for (int nt = 0; nt < 4; nt++)
#pragma unroll
            for (int e = 0; e < 4; e++) o[mt][nt][e] = 0.0f;

    const int vj  = lane & 15;
    const int vdh = ((lane >> 4) & 1) << 4;
#pragma unroll
    for (int kt = 0; kt < 4; kt++) {
        uint32_t vb[4][2];
#pragma unroll
        for (int p = 0; p < 2; p++)
            LDSM_X4_T(vb[2 * p][0], vb[2 * p][1], vb[2 * p + 1][0], vb[2 * p + 1][1],
                      v32 + (uint32_t)(kt * 16 + vj) * 80 + (uint32_t)(p * 32 + vdh));
#pragma unroll
        for (int mt = 0; mt < 4; mt++)
#pragma unroll
            for (int nt = 0; nt < 4; nt++)
                MMA16816(o[mt][nt], ph[mt][kt], vb[nt]);
    }

#pragma unroll
    for (int mt = 0; mt < 4; mt++) {
        float i0 = 1.0f / sum[mt][0];
        float i1 = 1.0f / sum[mt][1];
        int r0 = mt * 16 + r_lo, r1 = r0 + 8;
#pragma unroll
        for (int nt = 0; nt < 4; nt++) {
            int col = head * HD + nt * 8 + c_lo;
            if (r0 < LWIN)
                *(__half2*)(out + (size_t)(win * LWIN + r0) * CDIM + col) =
                    __floats2half2_rn(o[mt][nt][0] * i0, o[mt][nt][1] * i0);
            if (r1 < LWIN)
                *(__half2*)(out + (size_t)(win * LWIN + r1) * CDIM + col) =
                    __floats2half2_rn(o[mt][nt][2] * i1, o[mt][nt][3] * i1);
        }
    }
}

// ---------------- depthwise 3x3 conv: smem-tiled 8x8 pixels x 128 channels + GELU ----------
__global__ __launch_bounds__(256)
void dwconv_gelu(const __half* __restrict__ x, const float* __restrict__ kern,
                 const float* __restrict__ bias, __half* __restrict__ out)
{
    __shared__ __half2 s[64][101];
    const int cb   = blockIdx.x;
    const int tile = blockIdx.y;
    const int b    = blockIdx.z;
    const int th0  = (tile / 7) * 8;
    const int tw0  = (tile % 7) * 8;
    const int ch0  = cb * 128;
    const int tid  = threadIdx.x;

    for (int idx = tid; idx < 100 * 64; idx += 256) {
        int loc = idx >> 6;
        int pr  = idx & 63;
        int ly = loc / 10 - 1, lx = loc - (loc / 10) * 10 - 1;
        int ih = th0 + ly, iw = tw0 + lx;
        __half2 v = __float2half2_rn(0.0f);
        if ((unsigned)ih < HH && (unsigned)iw < WW)
            v = *(const __half2*)(x + ((size_t)b * NTOK + ih * WW + iw) * HID + ch0 + pr * 2);
        s[pr][loc] = v;
    }
    __syncthreads();

    const int pr = tid & 63;
    const int g  = tid >> 6;
    const int ch = ch0 + pr * 2;
    float k0[9], k1[9];
#pragma unroll
    for (int i = 0; i < 9; i++) { k0[i] = kern[ch * 9 + i]; k1[i] = kern[ch * 9 + 9 + i]; }
    float2 bb = *(const float2*)(bias + ch);

#pragma unroll
    for (int pp = 0; pp < 16; pp++) {
        int pix = g * 16 + pp;
        int py = pix >> 3, px = pix & 7;
        float a0 = bb.x, a1 = bb.y;
#pragma unroll
        for (int dh = 0; dh < 3; dh++)
#pragma unroll
            for (int dw = 0; dw < 3; dw++) {
                float2 v = __half22float2(s[pr][(py + dh) * 10 + px + dw]);
                a0 = fmaf(v.x, k0[dh * 3 + dw], a0);
                a1 = fmaf(v.y, k1[dh * 3 + dw], a1);
            }
        float g0 = 0.5f * a0 * (1.0f + erff(a0 * 0.70710678118654752f));
        float g1 = 0.5f * a1 * (1.0f + erff(a1 * 0.70710678118654752f));
        *(__half2*)(out + ((size_t)b * NTOK + (th0 + py) * WW + tw0 + px) * HID + ch) =
            __floats2half2_rn(g0, g1);
    }
}

// ---------------- launcher ----------------
extern "C" void kernel_launch(void* const* d_in, const int* in_sizes, int n_in,
                              void* d_out, int out_size)
{
    const float* x     = (const float*)d_in[0];
    const float* ln1g  = (const float*)d_in[1];
    const float* ln1b  = (const float*)d_in[2];
    const float* qkvw  = (const float*)d_in[3];
    const float* projw = (const float*)d_in[4];
    const float* projb = (const float*)d_in[5];
    const float* ln2g  = (const float*)d_in[6];
    const float* ln2b  = (const float*)d_in[7];
    const float* fc1w  = (const float*)d_in[8];
    const float* fc1b  = (const float*)d_in[9];
    const float* dwk   = (const float*)d_in[10];
    const float* dwb   = (const float*)d_in[11];
    const float* fc2w  = (const float*)d_in[12];
    const float* fc2b  = (const float*)d_in[13];
    float* out = (float*)d_out;

    __half *xw, *qkv, *attn, *xn2, *h1, *h2, *wqkv, *wproj, *wfc1, *wfc2;
    float  *x2;
    cudaGetSymbolAddress((void**)&xw,    g_xw);
    cudaGetSymbolAddress((void**)&qkv,   g_qkv);
    cudaGetSymbolAddress((void**)&attn,  g_attn);
    cudaGetSymbolAddress((void**)&x2,    g_x2);
    cudaGetSymbolAddress((void**)&xn2,   g_xn2);
    cudaGetSymbolAddress((void**)&h1,    g_h1);
    cudaGetSymbolAddress((void**)&h2,    g_h2);
    cudaGetSymbolAddress((void**)&wqkv,  g_wqkv);
    cudaGetSymbolAddress((void**)&wproj, g_wproj);
    cudaGetSymbolAddress((void**)&wfc1,  g_wfc1);
    cudaGetSymbolAddress((void**)&wfc2,  g_wfc2);

    cudaFuncSetAttribute(hgemm<0, CDIM, 3 * CDIM>, cudaFuncAttributeMaxDynamicSharedMemorySize, GEMM_SMEM);
    cudaFuncSetAttribute(hgemm<2, CDIM, CDIM>,     cudaFuncAttributeMaxDynamicSharedMemorySize, GEMM_SMEM);
    cudaFuncSetAttribute(hgemm<1, CDIM, HID>,      cudaFuncAttributeMaxDynamicSharedMemorySize, GEMM_SMEM);
    cudaFuncSetAttribute(hgemm<3, HID, CDIM>,      cudaFuncAttributeMaxDynamicSharedMemorySize, GEMM_SMEM);
    cudaFuncSetAttribute(attn_kernel,              cudaFuncAttributeMaxDynamicSharedMemorySize, ATT_SMEM);

    // 0: all weight preps (merged)
    wprep4<<<1728, dim3(32, 8)>>>(qkvw, wqkv, projw, wproj, fc1w, wfc1, fc2w, wfc2);
    // 1: LN1 + roll(-3,-3) + window partition (fp16 out)
    ln_kernel<true><<<MTOT / 8, 256>>>(x, ln1g, ln1b, xw);
    // 2: QKV GEMM
    hgemm<0, CDIM, 3 * CDIM><<<dim3(9, MTOT / 128), 256, GEMM_SMEM>>>(xw, wqkv, qkv, (const float*)0, (const float*)0);
    // 3: windowed attention (tensor cores, analytic shift mask)
    attn_kernel<<<dim3(1024, 3), 128, ATT_SMEM>>>(qkv, attn);
    // 4: proj GEMM + bias + window-reverse scatter + residual(x) -> x2 (fp32)
    hgemm<2, CDIM, CDIM><<<dim3(3, MTOT / 128), 256, GEMM_SMEM>>>(attn, wproj, x2, projb, x);
    // 5: LN2 (fp16 out)
    ln_kernel<false><<<MTOT / 8, 256>>>(x2, ln2g, ln2b, xn2);
    // 6: fc1 GEMM + bias
    hgemm<1, CDIM, HID><<<dim3(12, MTOT / 128), 256, GEMM_SMEM>>>(xn2, wfc1, h1, fc1b, (const float*)0);
    // 7: depthwise conv + bias + exact GELU (smem-tiled)
    dwconv_gelu<<<dim3(12, 49, BATCH), 256>>>(h1, dwk, dwb, h2);
    // 8: fc2 GEMM + bias + residual(x2) -> out (fp32)
    hgemm<3, HID, CDIM><<<dim3(3, MTOT / 128), 256, GEMM_SMEM>>>(h2, wfc2, out, fc2b, x2);
}

// round 17
// speedup vs baseline: 1.0305x; 1.0060x over previous
#include <cuda_runtime.h>
#include <cuda_fp16.h>
#include <math.h>
#include <stdint.h>

// ---------------- problem constants ----------------
#define BATCH 16
#define HH 56
#define WW 56
#define NTOK 3136            // 56*56
#define CDIM 384
#define HEADS 12
#define HD 32
#define WS 7
#define LWIN 49
#define HID 1536
#define MTOT 50176           // BATCH*NTOK = 392*128

// ---------------- scratch (static device memory; no allocations) ----------------
__device__ __align__(256) __half g_xw   [(size_t)MTOT * CDIM];       // LN1 + window partition
__device__ __align__(256) __half g_qkv  [(size_t)MTOT * 3 * CDIM];
__device__ __align__(256) __half g_attn [(size_t)MTOT * CDIM];       // attn out, window order
__device__ __align__(256) float  g_x2   [(size_t)MTOT * CDIM];       // fp32 residual spine
__device__ __align__(256) __half g_xn2  [(size_t)MTOT * CDIM];
__device__ __align__(256) __half g_h1   [(size_t)MTOT * HID];
__device__ __align__(256) __half g_h2   [(size_t)MTOT * HID];
// fp16 transposed weights: Wt[n][k] = W[k][n]
__device__ __align__(256) __half g_wqkv [(size_t)3 * CDIM * CDIM];
__device__ __align__(256) __half g_wproj[(size_t)CDIM * CDIM];
__device__ __align__(256) __half g_wfc1 [(size_t)HID * CDIM];
__device__ __align__(256) __half g_wfc2 [(size_t)CDIM * HID];

// ---------------- helpers ----------------
__device__ __forceinline__ uint32_t smem_u32(const void* p)
{
    uint32_t a;
    asm("{ .reg .u64 t; cvta.to.shared.u64 t, %1; cvt.u32.u64 %0, t; }" : "=r"(a) : "l"(p));
    return a;
}

__device__ __forceinline__ uint32_t f2h2(float a, float b)
{
    __half2 h = __floats2half2_rn(a, b);
    return *(uint32_t*)&h;
}

#define CP_ASYNC16(dst, src) \
    asm volatile("cp.async.cg.shared.global [%0], [%1], 16;" :: "r"(dst), "l"(src))
#define CP_COMMIT() asm volatile("cp.async.commit_group;" ::: "memory")
#define CP_WAIT1()  asm volatile("cp.async.wait_group 1;" ::: "memory")

#define LDSM_X4(r0, r1, r2, r3, addr) \
    asm volatile("ldmatrix.sync.aligned.m8n8.x4.shared.b16 {%0,%1,%2,%3}, [%4];" \
                 : "=r"(r0), "=r"(r1), "=r"(r2), "=r"(r3) : "r"(addr))

#define LDSM_X4_T(r0, r1, r2, r3, addr) \
    asm volatile("ldmatrix.sync.aligned.m8n8.x4.trans.shared.b16 {%0,%1,%2,%3}, [%4];" \
                 : "=r"(r0), "=r"(r1), "=r"(r2), "=r"(r3) : "r"(addr))

#define MMA16816(c, a, b) \
    asm volatile("mma.sync.aligned.m16n8k16.row.col.f32.f16.f16.f32 " \
                 "{%0,%1,%2,%3}, {%4,%5,%6,%7}, {%8,%9}, {%0,%1,%2,%3};" \
                 : "+f"((c)[0]), "+f"((c)[1]), "+f"((c)[2]), "+f"((c)[3]) \
                 : "r"((a)[0]), "r"((a)[1]), "r"((a)[2]), "r"((a)[3]), \
                   "r"((b)[0]), "r"((b)[1]))

// window-order row -> spatial row (window reverse, NO un-shift, per reference)
__device__ __forceinline__ int map_win_to_spatial(int row)
{
    int b  = row / NTOK;
    int t  = row - b * NTOK;
    int wi = t / LWIN;
    int p  = t - wi * LWIN;
    int pr = p / WS;
    int pc = p - pr * WS;
    int h  = (wi >> 3) * WS + pr;
    int w  = (wi & 7)  * WS + pc;
    return b * NTOK + h * WW + w;
}

// ---------------- merged weight prep: all four fp32 [K,N] -> fp16 [N,K] transposes ---------
__global__ __launch_bounds__(256)
void wprep4(const float* __restrict__ Wq, __half* __restrict__ Tq,
            const float* __restrict__ Wp, __half* __restrict__ Tp,
            const float* __restrict__ W1, __half* __restrict__ T1,
            const float* __restrict__ W2, __half* __restrict__ T2)
{
    __shared__ float t[32][33];
    int bidx = blockIdx.x;
    const float* W; __half* Wt; int K, N, nx, r;
    if (bidx < 432)       { W = Wq; Wt = Tq; K = 384;  N = 1152; nx = 36; r = bidx; }
    else if (bidx < 576)  { W = Wp; Wt = Tp; K = 384;  N = 384;  nx = 12; r = bidx - 432; }
    else if (bidx < 1152) { W = W1; Wt = T1; K = 384;  N = 1536; nx = 48; r = bidx - 576; }
    else                  { W = W2; Wt = T2; K = 1536; N = 384;  nx = 12; r = bidx - 1152; }
    int n0 = (r % nx) * 32, k0 = (r / nx) * 32;
    int tx = threadIdx.x, ty = threadIdx.y;   // 32 x 8
#pragma unroll
    for (int i = 0; i < 32; i += 8)
        t[ty + i][tx] = W[(size_t)(k0 + ty + i) * N + n0 + tx];
    __syncthreads();
#pragma unroll
    for (int i = 0; i < 32; i += 8)
        Wt[(size_t)(n0 + ty + i) * K + k0 + tx] = __float2half(t[tx][ty + i]);
}

// ---------------- LayerNorm: warp per row (optionally fused shift + window partition) -------
template <bool SHIFT>
__global__ __launch_bounds__(256)
void ln_kernel(const float* __restrict__ x, const float* __restrict__ g,
               const float* __restrict__ b, __half* __restrict__ out)
{
    const int warp = threadIdx.x >> 5;
    const int lane = threadIdx.x & 31;
    const int row  = blockIdx.x * 8 + warp;
    int srow;
    if (SHIFT) {
        int bb = row / NTOK;
        int t  = row - bb * NTOK;
        int wi = t / LWIN;
        int p  = t - wi * LWIN;
        int pr = p / WS;
        int pc = p - pr * WS;
        int h  = (wi >> 3) * WS + pr + 3; if (h >= HH) h -= HH;
        int w  = (wi & 7)  * WS + pc + 3; if (w >= WW) w -= WW;
        srow = bb * NTOK + h * WW + w;
    } else {
        srow = row;
    }
    const float4* xr = (const float4*)(x + (size_t)srow * CDIM);
    float4 v[3];
    float s = 0.0f, ss = 0.0f;
#pragma unroll
    for (int w = 0; w < 3; w++) {
        v[w] = xr[lane + w * 32];
        s  += v[w].x + v[w].y + v[w].z + v[w].w;
        ss += v[w].x * v[w].x + v[w].y * v[w].y + v[w].z * v[w].z + v[w].w * v[w].w;
    }
#pragma unroll
    for (int off = 16; off; off >>= 1) {
        s  += __shfl_xor_sync(0xffffffffu, s,  off);
        ss += __shfl_xor_sync(0xffffffffu, ss, off);
    }
    const float m   = s * (1.0f / CDIM);
    const float inv = rsqrtf(ss * (1.0f / CDIM) - m * m + 1e-5f);
    uint2* o = (uint2*)(out + (size_t)row * CDIM);
    const float4* gp = (const float4*)g;
    const float4* bp = (const float4*)b;
#pragma unroll
    for (int w = 0; w < 3; w++) {
        float4 gg = gp[lane + w * 32];
        float4 bb = bp[lane + w * 32];
        float o0 = (v[w].x - m) * inv * gg.x + bb.x;
        float o1 = (v[w].y - m) * inv * gg.y + bb.y;
        float o2 = (v[w].z - m) * inv * gg.z + bb.z;
        float o3 = (v[w].w - m) * inv * gg.w + bb.w;
        uint2 u;
        ((__half2*)&u)[0] = __floats2half2_rn(o0, o1);
        ((__half2*)&u)[1] = __floats2half2_rn(o2, o3);
        o[lane + w * 32] = u;
    }
}

// ---------------- fp16 HMMA GEMM: 128x128x64 CTA tile, 4 warps (64x64 warp tile), ----------
// 3-stage cp.async, 2 CTAs/SM, smem-staged epilogue. Halves per-SM ldsm traffic vs
// the 8-warp/32x64 shape while keeping the 2-CTA latency overlap.
#define BMM 128
#define BNN 128
#define BKK 64
#define STG 3
#define STG_BYTES 16384                   // 128 rows * 128 B
#define GEMM_SMEM (STG * 2 * STG_BYTES)   // 98304

template <int MODE, int K, int N>
__global__ __launch_bounds__(128, 2)
void hgemm(const __half* __restrict__ A, const __half* __restrict__ Bw,
           void* __restrict__ Cout, const float* __restrict__ bias,
           const float* __restrict__ resid)
{
    extern __shared__ char smem[];
    const uint32_t sA = smem_u32(smem);
    const uint32_t sB = sA + STG * STG_BYTES;

    const int tid  = threadIdx.x;
    const int wid  = tid >> 5;           // 0..3
    const int lane = tid & 31;
    const int bm   = blockIdx.y * BMM;
    const int bn   = blockIdx.x * BNN;
    const int wm0  = (wid & 1) * 64;     // warp row offset
    const int wn0  = (wid >> 1) * 64;    // warp col offset

    // global load: 1024 16B-chunks per tile, 8 per thread
    const int lc = tid & 7;
    const int r0 = tid >> 3;             // 0..15; rows r0 + q*16
    uint32_t so[8];
#pragma unroll
    for (int q = 0; q < 8; q++) {
        int row = r0 + q * 16;
        so[q] = (uint32_t)row * 128 + (uint32_t)((lc ^ (row & 7)) << 4);
    }

    constexpr int NC = K / BKK;

#pragma unroll
    for (int c = 0; c < 2; c++) {
        const __half* Ag = A  + (size_t)(bm + r0) * K + c * BKK + lc * 8;
        const __half* Bg = Bw + (size_t)(bn + r0) * K + c * BKK + lc * 8;
        uint32_t da = sA + c * STG_BYTES;
        uint32_t db = sB + c * STG_BYTES;
#pragma unroll
        for (int q = 0; q < 8; q++) {
            CP_ASYNC16(da + so[q], Ag + (size_t)(q * 16) * K);
            CP_ASYNC16(db + so[q], Bg + (size_t)(q * 16) * K);
        }
        CP_COMMIT();
    }

    float acc[4][8][4];
#pragma unroll
    for (int i = 0; i < 4; i++)
#pragma unroll
        for (int j = 0; j < 8; j++)
#pragma unroll
            for (int r = 0; r < 4; r++) acc[i][j][r] = 0.0f;

    // per-lane ldmatrix row/chunk components (R6/R9-verified 4-fi A mapping)
    const int a_row_l = lane & 15;                              // + fi*16
    const int a_chk_l = (lane >> 4) & 1;                        // + 2*ks
    const int b_row_l = (((lane >> 4) & 1) << 3) + (lane & 7);  // + nj*16
    const int b_chk_l = (lane >> 3) & 1;                        // + 2*ks

    for (int c = 0; c < NC; c++) {
        const int st = c % STG;
        CP_WAIT1();
        __syncthreads();

        if (c + 2 < NC) {
            const int cc = c + 2, s2 = cc % STG;
            const __half* Ag = A  + (size_t)(bm + r0) * K + cc * BKK + lc * 8;
            const __half* Bg = Bw + (size_t)(bn + r0) * K + cc * BKK + lc * 8;
            uint32_t da = sA + s2 * STG_BYTES;
            uint32_t db = sB + s2 * STG_BYTES;
#pragma unroll
            for (int q = 0; q < 8; q++) {
                CP_ASYNC16(da + so[q], Ag + (size_t)(q * 16) * K);
                CP_ASYNC16(db + so[q], Bg + (size_t)(q * 16) * K);
            }
        }
        CP_COMMIT();

        const uint32_t ab = sA + st * STG_BYTES;
        const uint32_t bb = sB + st * STG_BYTES;
#pragma unroll
        for (int ks = 0; ks < 4; ks++) {
            uint32_t a[4][4], b[8][2];
#pragma unroll
            for (int fi = 0; fi < 4; fi++) {
                int row = wm0 + fi * 16 + a_row_l;
                int chk = 2 * ks + a_chk_l;
                uint32_t ad = ab + (uint32_t)row * 128 + (uint32_t)((chk ^ (row & 7)) << 4);
                LDSM_X4(a[fi][0], a[fi][1], a[fi][2], a[fi][3], ad);
            }
#pragma unroll
            for (int nj = 0; nj < 4; nj++) {
                int row = wn0 + nj * 16 + b_row_l;
                int chk = 2 * ks + b_chk_l;
                uint32_t bd = bb + (uint32_t)row * 128 + (uint32_t)((chk ^ (row & 7)) << 4);
                LDSM_X4(b[nj * 2][0], b[nj * 2][1], b[nj * 2 + 1][0], b[nj * 2 + 1][1], bd);
            }
#pragma unroll
            for (int fi = 0; fi < 4; fi++)
#pragma unroll
                for (int j = 0; j < 8; j++)
                    MMA16816(acc[fi][j], a[fi], b[j]);
        }
    }

    // ---------------- epilogue: stage through smem for coalesced global I/O ----------------
    __syncthreads();
    if (MODE <= 1) {
#pragma unroll
        for (int fi = 0; fi < 4; fi++)
#pragma unroll
            for (int h = 0; h < 2; h++) {
                int row = wm0 + fi * 16 + (lane >> 2) + h * 8;
#pragma unroll
                for (int j = 0; j < 8; j++) {
                    int col = wn0 + j * 8 + (lane & 3) * 2;
                    float v0 = acc[fi][j][h * 2];
                    float v1 = acc[fi][j][h * 2 + 1];
                    if (MODE == 1) { v0 += bias[bn + col]; v1 += bias[bn + col + 1]; }
                    *(__half2*)(smem + row * 272 + col * 2) = __floats2half2_rn(v0, v1);
                }
            }
        __syncthreads();
        __half* Ch = (__half*)Cout;
#pragma unroll
        for (int k = 0; k < 16; k++) {
            int idx = tid + k * 128;
            int row = idx >> 4, seg = idx & 15;
            *(uint4*)(Ch + (size_t)(bm + row) * N + bn + seg * 8) =
                *(uint4*)(smem + row * 272 + seg * 16);
        }
    } else {
#pragma unroll
        for (int fi = 0; fi < 4; fi++)
#pragma unroll
            for (int h = 0; h < 2; h++) {
                int row = wm0 + fi * 16 + (lane >> 2) + h * 8;
#pragma unroll
                for (int j = 0; j < 8; j++) {
                    int col = wn0 + j * 8 + (lane & 3) * 2;
                    float2 v;
                    v.x = acc[fi][j][h * 2];
                    v.y = acc[fi][j][h * 2 + 1];
                    *(float2*)(smem + row * 544 + col * 4) = v;
                }
            }
        __syncthreads();
        float* Cf = (float*)Cout;
        const float4 bb4 = *(const float4*)(bias + bn + lane * 4);
        for (int row = wid; row < 128; row += 4) {
            int orow = (MODE == 2) ? map_win_to_spatial(bm + row) : (bm + row);
            float4 v  = *(float4*)(smem + row * 544 + lane * 16);
            float4 rr = *(const float4*)(resid + (size_t)orow * N + bn + lane * 4);
            v.x += bb4.x + rr.x; v.y += bb4.y + rr.y;
            v.z += bb4.z + rr.z; v.w += bb4.w + rr.w;
            *(float4*)(Cf + (size_t)orow * N + bn + lane * 4) = v;
        }
    }
}

// ---------------- windowed attention on tensor cores (Round-16 proven) ----------------
#define ATT_HB 15360                      // per-head smem: 3 tensors * 64 rows * 80 B
#define ATT_SMEM (4 * ATT_HB)             // 61440

__global__ __launch_bounds__(128, 3)
void attn_kernel(const __half* __restrict__ qkv, __half* __restrict__ out)
{
    extern __shared__ char sm[];
    __shared__ int rg[LWIN];
    const int win  = blockIdx.x;
    const int tid  = threadIdx.x;
    const int wid  = tid >> 5;
    const int lane = tid & 31;
    const int head = blockIdx.y * 4 + wid;

    if (tid < LWIN) {
        int wi = win & 63;
        int h = (wi >> 3) * WS + tid / WS;
        int w = (wi & 7)  * WS + tid % WS;
        int sh = (h < HH - WS) ? 0 : ((h < HH - 3) ? 1 : 2);
        int sw = (w < WW - WS) ? 0 : ((w < WW - 3) ? 1 : 2);
        rg[tid] = sh * 3 + sw;
    }

    char* Qs = sm + wid * ATT_HB;
    char* Ks = Qs + 5120;
    char* Vs = Qs + 10240;
    for (int i = lane; i < 75; i += 32)
        *(uint4*)(Vs + 49 * 80 + i * 16) = make_uint4(0u, 0u, 0u, 0u);
    const __half* src = qkv + (size_t)win * LWIN * (3 * CDIM) + head * HD;
    for (int c = lane; c < 196; c += 32) {
        int row = c >> 2, part = c & 3;
        const __half* s = src + (size_t)row * (3 * CDIM) + part * 8;
        *(uint4*)(Qs + row * 80 + part * 16) = *(const uint4*)(s);
        *(uint4*)(Ks + row * 80 + part * 16) = *(const uint4*)(s + CDIM);
        *(uint4*)(Vs + row * 80 + part * 16) = *(const uint4*)(s + 2 * CDIM);
    }
    __syncthreads();

    const uint32_t q32 = smem_u32(Qs), k32 = smem_u32(Ks), v32 = smem_u32(Vs);
    const int a_row = (lane & 8) + (lane & 7);
    const int a_chk = (lane >> 4) & 1;
    const int b_row = (((lane >> 4) & 1) << 3) + (lane & 7);
    const int b_chk = (lane >> 3) & 1;

    float c[4][7][4];
#pragma unroll
    for (int mt = 0; mt < 4; mt++)
#pragma unroll
        for (int nt = 0; nt < 7; nt++)
#pragma unroll
            for (int e = 0; e < 4; e++) c[mt][nt][e] = 0.0f;

#pragma unroll
    for (int kt = 0; kt < 2; kt++) {
        uint32_t qa[4][4], kb[8][2];
#pragma unroll
        for (int mt = 0; mt < 4; mt++)
            LDSM_X4(qa[mt][0], qa[mt][1], qa[mt][2], qa[mt][3],
                    q32 + (uint32_t)(mt * 16 + a_row) * 80 + (uint32_t)(2 * kt + a_chk) * 16);
#pragma unroll
        for (int p = 0; p < 4; p++)
            LDSM_X4(kb[2 * p][0], kb[2 * p][1], kb[2 * p + 1][0], kb[2 * p + 1][1],
                    k32 + (uint32_t)(p * 16 + b_row) * 80 + (uint32_t)(2 * kt + b_chk) * 16);
#pragma unroll
        for (int mt = 0; mt < 4; mt++)
#pragma unroll
            for (int nt = 0; nt < 7; nt++)
                MMA16816(c[mt][nt], qa[mt], kb[nt]);
    }

    const int r_lo = lane >> 2;
    const int c_lo = (lane & 3) << 1;
    const float scale = 0.17677669529663687f;
    int rgr[8];
#pragma unroll
    for (int mt = 0; mt < 4; mt++) {
        int r0 = mt * 16 + r_lo, r1 = r0 + 8;
        rgr[mt * 2]     = rg[r0 < LWIN ? r0 : 48];
        rgr[mt * 2 + 1] = rg[r1 < LWIN ? r1 : 48];
    }
    int  rgc[7][2];
    bool jv[7][2];
#pragma unroll
    for (int nt = 0; nt < 7; nt++)
#pragma unroll
        for (int e = 0; e < 2; e++) {
            int j = nt * 8 + c_lo + e;
            jv[nt][e]  = (j < LWIN);
            rgc[nt][e] = rg[j < LWIN ? j : 48];
        }

    float sum[4][2];
#pragma unroll
    for (int mt = 0; mt < 4; mt++) {
#pragma unroll
        for (int h = 0; h < 2; h++) {
            float m = -1e30f;
#pragma unroll
            for (int nt = 0; nt < 7; nt++)
#pragma unroll
                for (int e = 0; e < 2; e++) {
                    float v = c[mt][nt][h * 2 + e] * scale;
                    if (!jv[nt][e]) v = -1e30f;
                    else if (rgr[mt * 2 + h] != rgc[nt][e]) v -= 100.0f;
                    c[mt][nt][h * 2 + e] = v;
                    m = fmaxf(m, v);
                }
            m = fmaxf(m, __shfl_xor_sync(0xffffffffu, m, 1));
            m = fmaxf(m, __shfl_xor_sync(0xffffffffu, m, 2));
            float s = 0.0f;
#pragma unroll
            for (int nt = 0; nt < 7; nt++)
#pragma unroll
                for (int e = 0; e < 2; e++) {
                    float p = __expf(c[mt][nt][h * 2 + e] - m);
                    c[mt][nt][h * 2 + e] = p;
                    s += p;
                }
            s += __shfl_xor_sync(0xffffffffu, s, 1);
            s += __shfl_xor_sync(0xffffffffu, s, 2);
            sum[mt][h] = s;
        }
    }

    uint32_t ph[4][4][4];
#pragma unroll
    for (int mt = 0; mt < 4; mt++)
#pragma unroll
        for (int k2 = 0; k2 < 4; k2++) {
            int nt0 = 2 * k2, nt1 = nt0 + 1;
            ph[mt][k2][0] = f2h2(c[mt][nt0][0], c[mt][nt0][1]);
            ph[mt][k2][1] = f2h2(c[mt][nt0][2], c[mt][nt0][3]);
            ph[mt][k2][2] = (nt1 < 7) ? f2h2(c[mt][nt1][0], c[mt][nt1][1]) : 0u;
            ph[mt][k2][3] = (nt1 < 7) ? f2h2(c[mt][nt1][2], c[mt][nt1][3]) : 0u;
        }

    float o[4][4][4];
#pragma unroll
    for (int mt = 0; mt < 4; mt++)
#pragma unroll
        for (int nt = 0; nt < 4; nt++)
#pragma unroll
            for (int e = 0; e < 4; e++) o[mt][nt][e] = 0.0f;

    const int vj  = lane & 15;
    const int vdh = ((lane >> 4) & 1) << 4;
#pragma unroll
    for (int kt = 0; kt < 4; kt++) {
        uint32_t vb[4][2];
#pragma unroll
        for (int p = 0; p < 2; p++)
            LDSM_X4_T(vb[2 * p][0], vb[2 * p][1], vb[2 * p + 1][0], vb[2 * p + 1][1],
                      v32 + (uint32_t)(kt * 16 + vj) * 80 + (uint32_t)(p * 32 + vdh));
#pragma unroll
        for (int mt = 0; mt < 4; mt++)
#pragma unroll
            for (int nt = 0; nt < 4; nt++)
                MMA16816(o[mt][nt], ph[mt][kt], vb[nt]);
    }

#pragma unroll
    for (int mt = 0; mt < 4; mt++) {
        float i0 = 1.0f / sum[mt][0];
        float i1 = 1.0f / sum[mt][1];
        int r0 = mt * 16 + r_lo, r1 = r0 + 8;
#pragma unroll
        for (int nt = 0; nt < 4; nt++) {
            int col = head * HD + nt * 8 + c_lo;
            if (r0 < LWIN)
                *(__half2*)(out + (size_t)(win * LWIN + r0) * CDIM + col) =
                    __floats2half2_rn(o[mt][nt][0] * i0, o[mt][nt][1] * i0);
            if (r1 < LWIN)
                *(__half2*)(out + (size_t)(win * LWIN + r1) * CDIM + col) =
                    __floats2half2_rn(o[mt][nt][2] * i1, o[mt][nt][3] * i1);
        }
    }
}

// ---------------- depthwise 3x3 conv: smem-tiled 8x8 pixels x 128 channels + GELU ----------
__global__ __launch_bounds__(256)
void dwconv_gelu(const __half* __restrict__ x, const float* __restrict__ kern,
                 const float* __restrict__ bias, __half* __restrict__ out)
{
    __shared__ __half2 s[64][101];
    const int cb   = blockIdx.x;
    const int tile = blockIdx.y;
    const int b    = blockIdx.z;
    const int th0  = (tile / 7) * 8;
    const int tw0  = (tile % 7) * 8;
    const int ch0  = cb * 128;
    const int tid  = threadIdx.x;

    for (int idx = tid; idx < 100 * 64; idx += 256) {
        int loc = idx >> 6;
        int pr  = idx & 63;
        int ly = loc / 10 - 1, lx = loc - (loc / 10) * 10 - 1;
        int ih = th0 + ly, iw = tw0 + lx;
        __half2 v = __float2half2_rn(0.0f);
        if ((unsigned)ih < HH && (unsigned)iw < WW)
            v = *(const __half2*)(x + ((size_t)b * NTOK + ih * WW + iw) * HID + ch0 + pr * 2);
        s[pr][loc] = v;
    }
    __syncthreads();

    const int pr = tid & 63;
    const int g  = tid >> 6;
    const int ch = ch0 + pr * 2;
    float k0[9], k1[9];
#pragma unroll
    for (int i = 0; i < 9; i++) { k0[i] = kern[ch * 9 + i]; k1[i] = kern[ch * 9 + 9 + i]; }
    float2 bb = *(const float2*)(bias + ch);

#pragma unroll
    for (int pp = 0; pp < 16; pp++) {
        int pix = g * 16 + pp;
        int py = pix >> 3, px = pix & 7;
        float a0 = bb.x, a1 = bb.y;
#pragma unroll
        for (int dh = 0; dh < 3; dh++)
#pragma unroll
            for (int dw = 0; dw < 3; dw++) {
                float2 v = __half22float2(s[pr][(py + dh) * 10 + px + dw]);
                a0 = fmaf(v.x, k0[dh * 3 + dw], a0);
                a1 = fmaf(v.y, k1[dh * 3 + dw], a1);
            }
        float g0 = 0.5f * a0 * (1.0f + erff(a0 * 0.70710678118654752f));
        float g1 = 0.5f * a1 * (1.0f + erff(a1 * 0.70710678118654752f));
        *(__half2*)(out + ((size_t)b * NTOK + (th0 + py) * WW + tw0 + px) * HID + ch) =
            __floats2half2_rn(g0, g1);
    }
}

// ---------------- launcher ----------------
extern "C" void kernel_launch(void* const* d_in, const int* in_sizes, int n_in,
                              void* d_out, int out_size)
{
    const float* x     = (const float*)d_in[0];
    const float* ln1g  = (const float*)d_in[1];
    const float* ln1b  = (const float*)d_in[2];
    const float* qkvw  = (const float*)d_in[3];
    const float* projw = (const float*)d_in[4];
    const float* projb = (const float*)d_in[5];
    const float* ln2g  = (const float*)d_in[6];
    const float* ln2b  = (const float*)d_in[7];
    const float* fc1w  = (const float*)d_in[8];
    const float* fc1b  = (const float*)d_in[9];
    const float* dwk   = (const float*)d_in[10];
    const float* dwb   = (const float*)d_in[11];
    const float* fc2w  = (const float*)d_in[12];
    const float* fc2b  = (const float*)d_in[13];
    float* out = (float*)d_out;

    __half *xw, *qkv, *attn, *xn2, *h1, *h2, *wqkv, *wproj, *wfc1, *wfc2;
    float  *x2;
    cudaGetSymbolAddress((void**)&xw,    g_xw);
    cudaGetSymbolAddress((void**)&qkv,   g_qkv);
    cudaGetSymbolAddress((void**)&attn,  g_attn);
    cudaGetSymbolAddress((void**)&x2,    g_x2);
    cudaGetSymbolAddress((void**)&xn2,   g_xn2);
    cudaGetSymbolAddress((void**)&h1,    g_h1);
    cudaGetSymbolAddress((void**)&h2,    g_h2);
    cudaGetSymbolAddress((void**)&wqkv,  g_wqkv);
    cudaGetSymbolAddress((void**)&wproj, g_wproj);
    cudaGetSymbolAddress((void**)&wfc1,  g_wfc1);
    cudaGetSymbolAddress((void**)&wfc2,  g_wfc2);

    cudaFuncSetAttribute(hgemm<0, CDIM, 3 * CDIM>, cudaFuncAttributeMaxDynamicSharedMemorySize, GEMM_SMEM);
    cudaFuncSetAttribute(hgemm<2, CDIM, CDIM>,     cudaFuncAttributeMaxDynamicSharedMemorySize, GEMM_SMEM);
    cudaFuncSetAttribute(hgemm<1, CDIM, HID>,      cudaFuncAttributeMaxDynamicSharedMemorySize, GEMM_SMEM);
    cudaFuncSetAttribute(hgemm<3, HID, CDIM>,      cudaFuncAttributeMaxDynamicSharedMemorySize, GEMM_SMEM);
    cudaFuncSetAttribute(attn_kernel,              cudaFuncAttributeMaxDynamicSharedMemorySize, ATT_SMEM);

    // 0: all weight preps (merged)
    wprep4<<<1728, dim3(32, 8)>>>(qkvw, wqkv, projw, wproj, fc1w, wfc1, fc2w, wfc2);
    // 1: LN1 + roll(-3,-3) + window partition (fp16 out)
    ln_kernel<true><<<MTOT / 8, 256>>>(x, ln1g, ln1b, xw);
    // 2: QKV GEMM
    hgemm<0, CDIM, 3 * CDIM><<<dim3(9, MTOT / 128), 128, GEMM_SMEM>>>(xw, wqkv, qkv, (const float*)0, (const float*)0);
    // 3: windowed attention (tensor cores, analytic shift mask)
    attn_kernel<<<dim3(1024, 3), 128, ATT_SMEM>>>(qkv, attn);
    // 4: proj GEMM + bias + window-reverse scatter + residual(x) -> x2 (fp32)
    hgemm<2, CDIM, CDIM><<<dim3(3, MTOT / 128), 128, GEMM_SMEM>>>(attn, wproj, x2, projb, x);
    // 5: LN2 (fp16 out)
    ln_kernel<false><<<MTOT / 8, 256>>>(x2, ln2g, ln2b, xn2);
    // 6: fc1 GEMM + bias
    hgemm<1, CDIM, HID><<<dim3(12, MTOT / 128), 128, GEMM_SMEM>>>(xn2, wfc1, h1, fc1b, (const float*)0);
    // 7: depthwise conv + bias + exact GELU (smem-tiled)
    dwconv_gelu<<<dim3(12, 49, BATCH), 256>>>(h1, dwk, dwb, h2);
    // 8: fc2 GEMM + bias + residual(x2) -> out (fp32)
    hgemm<3, HID, CDIM><<<dim3(3, MTOT / 128), 128, GEMM_SMEM>>>(h2, wfc2, out, fc2b, x2);
}